// round 17
// baseline (speedup 1.0000x reference)
#include <cuda_runtime.h>
#include <math.h>

#define NN 100000
#define NE 3200000
#define EPS 1e-5f

// ---------------- scratch (static device globals; no allocation) -------------
__device__ int   g_cnt[NN];               // zero-init at load; scan_apply resets each run
__device__ int   g_part[128];             // per-block partial sums for the scan
__device__ int   g_rowptr[NN + 1];
__device__ int   g_cursor[NN];
__device__ float g_dis[NN];
__device__ __align__(16)  int2  g_edge[NE + 8];   // {src, dis[src]}, +8 zero padding
__device__ __align__(256) float g_T[(size_t)NN * 128];
__device__ __align__(256) float g_A[(size_t)NN * 128];
__device__ float g_t4[NN];

// ---------------- fused gemm1 (x@W1, 128->32, R=4, K-chunked) + degree count --
// Dynamic smem: [Ws: 128*32 f32][xs: 128*(64+1) f32]  = 49664 B
__global__ void __launch_bounds__(256) k_gemm1_count(
        const float* __restrict__ in, const float* __restrict__ W,
        float* __restrict__ t,
        const int* __restrict__ dst, int* cnt) {
    constexpr int DIN = 128, DOUT = 32, R = 4, KC = 64;
    constexpr int OX  = DOUT / 4;        // 8
    constexpr int NPB = (256 / OX) * R;  // 128
    constexpr int XP  = KC + 1;          // 65
    extern __shared__ float dynsm[];
    float* Ws = dynsm;                   // 128*32
    float* xs = dynsm + DIN * DOUT;      // 128*65

    const int tid = threadIdx.x;
    for (int i = tid; i < DIN * DOUT; i += 256) Ws[i] = W[i];
    __syncthreads();

    const int base = blockIdx.x * NPB;
    const int ox = tid % OX;
    const int r0 = (tid / OX) * R;

    float4 acc[R];
#pragma unroll
    for (int j = 0; j < R; ++j) acc[j] = make_float4(0.f, 0.f, 0.f, 0.f);

#pragma unroll
    for (int c = 0; c < DIN / KC; ++c) {
        // load this K-chunk of x for all 128 nodes
        for (int i = tid; i < NPB * KC; i += 256) {
            int r = i / KC, k = i - r * KC;
            int node = base + r;
            xs[r * XP + k] = (node < NN) ? in[(size_t)node * DIN + c * KC + k] : 0.0f;
        }
        __syncthreads();
#pragma unroll 4
        for (int k = 0; k < KC; ++k) {
            float4 w = *reinterpret_cast<const float4*>(&Ws[(c * KC + k) * DOUT + ox * 4]);
#pragma unroll
            for (int j = 0; j < R; ++j) {
                float xv = xs[(r0 + j) * XP + k];
                acc[j].x += xv * w.x; acc[j].y += xv * w.y;
                acc[j].z += xv * w.z; acc[j].w += xv * w.w;
            }
        }
        __syncthreads();
    }

#pragma unroll
    for (int j = 0; j < R; ++j) {
        int node = base + r0 + j;
        if (node < NN)
            *reinterpret_cast<float4*>(&t[(size_t)node * DOUT + ox * 4]) = acc[j];
    }

    // ---- degree count (grid-stride, 4 edges per step via int4) ----
    const int gtid = blockIdx.x * 256 + tid;
    const int nth  = gridDim.x * 256;
    for (int i = gtid; i < NE / 4; i += nth) {
        int4 d4 = reinterpret_cast<const int4*>(dst)[i];
        atomicAdd(&cnt[d4.x], 1);
        atomicAdd(&cnt[d4.y], 1);
        atomicAdd(&cnt[d4.z], 1);
        atomicAdd(&cnt[d4.w], 1);
    }
}

// ---------------- multi-block scan (2 kernels) --------------------------------
__global__ void __launch_bounds__(1024) k_scan_part(const int* __restrict__ cnt,
                                                    int* partials) {
    __shared__ int sh[1024];
    int i = blockIdx.x * 1024 + threadIdx.x;
    sh[threadIdx.x] = (i < NN) ? cnt[i] : 0;
    __syncthreads();
    for (int o = 512; o > 0; o >>= 1) {
        if (threadIdx.x < o) sh[threadIdx.x] += sh[threadIdx.x + o];
        __syncthreads();
    }
    if (threadIdx.x == 0) partials[blockIdx.x] = sh[0];
}

__global__ void __launch_bounds__(1024) k_scan_apply(int* cnt,
        const int* __restrict__ partials,
        int* rowptr, int* cursor, float* dis) {
    constexpr int NBLK = (NN + 1023) / 1024;   // 98
    __shared__ int sp[128];
    __shared__ int sh[1024];
    const int b = blockIdx.x, t = threadIdx.x;
    if (t < 128) sp[t] = (t < NBLK) ? partials[t] : 0;
    __syncthreads();
    for (int o = 1; o < 128; o <<= 1) {
        int v = 0;
        if (t < 128 && t >= o) v = sp[t - o];
        __syncthreads();
        if (t < 128 && t >= o) sp[t] += v;
        __syncthreads();
    }
    const int base = (b > 0) ? sp[b - 1] : 0;
    const int i = b * 1024 + t;
    const int c = (i < NN) ? cnt[i] : 0;
    sh[t] = c;
    __syncthreads();
    for (int o = 1; o < 1024; o <<= 1) {
        int v = 0;
        if (t >= o) v = sh[t - o];
        __syncthreads();
        if (t >= o) sh[t] += v;
        __syncthreads();
    }
    if (i < NN) {
        int pos = base + sh[t] - c;            // exclusive prefix
        rowptr[i] = pos;
        cursor[i] = pos;
        cnt[i] = 0;
        dis[i] = rsqrtf((float)(c + 1));
    }
    if (b == 0 && t == 0) rowptr[NN] = sp[NBLK - 1];
}

// ---------------- permute: edges[pos] = {src, dis[src]} -----------------------
__global__ void __launch_bounds__(256) k_permute(const int* __restrict__ src,
                                                 const int* __restrict__ dst,
                                                 const float* __restrict__ dis,
                                                 int* cursor, int2* edges) {
    int e = blockIdx.x * blockDim.x + threadIdx.x;
    if (e >= NE) return;
    int s = src[e], d = dst[e];
    int pos = atomicAdd(&cursor[d], 1);
    edges[pos] = make_int2(s, __float_as_int(dis[s]));
}

// ---------------- sub-warp CSR gather: G nodes/warp ---------------------------
template<int DIM, int G, bool ACT>
__global__ void __launch_bounds__(256) k_gatherG(const float* __restrict__ t,
                         const int* __restrict__ rowptr,
                         const int2* __restrict__ edges,
                         const float* __restrict__ dis,
                         const float* __restrict__ b,
                         const float* __restrict__ bg, const float* __restrict__ bbe,
                         const float* __restrict__ bm, const float* __restrict__ bv,
                         float* __restrict__ outp) {
    constexpr int L = 32 / G;          // lanes per node
    static_assert(DIM == L * 4, "each lane owns a float4");
    const int wid  = (blockIdx.x * blockDim.x + threadIdx.x) >> 5;
    const int lane = threadIdx.x & 31;
    const int sub  = lane / L;
    const int sl   = lane % L;
    const int node = wid * G + sub;
    if (node >= NN) return;
    const int beg = rowptr[node], end = rowptr[node + 1];
    const float dn = dis[node];
    const int col = sl * 4;

    float4 p_scale, p_shift;
    if (ACT) {
        float ss0 = bg[col+0] * rsqrtf(bv[col+0] + EPS);
        float ss1 = bg[col+1] * rsqrtf(bv[col+1] + EPS);
        float ss2 = bg[col+2] * rsqrtf(bv[col+2] + EPS);
        float ss3 = bg[col+3] * rsqrtf(bv[col+3] + EPS);
        p_scale = make_float4(ss0, ss1, ss2, ss3);
        p_shift = make_float4(ss0 * (b[col+0] - bm[col+0]) + bbe[col+0],
                              ss1 * (b[col+1] - bm[col+1]) + bbe[col+1],
                              ss2 * (b[col+2] - bm[col+2]) + bbe[col+2],
                              ss3 * (b[col+3] - bm[col+3]) + bbe[col+3]);
    }

    float4 a0 = make_float4(0.f, 0.f, 0.f, 0.f);
    float4 a1 = make_float4(0.f, 0.f, 0.f, 0.f);

    int i = beg;
    for (; i + 4 <= end; i += 4) {
        int2 e0 = edges[i],   e1 = edges[i+1];
        int2 e2 = edges[i+2], e3 = edges[i+3];
        float4 v0 = *reinterpret_cast<const float4*>(&t[(size_t)e0.x * DIM + col]);
        float4 v1 = *reinterpret_cast<const float4*>(&t[(size_t)e1.x * DIM + col]);
        float4 v2 = *reinterpret_cast<const float4*>(&t[(size_t)e2.x * DIM + col]);
        float4 v3 = *reinterpret_cast<const float4*>(&t[(size_t)e3.x * DIM + col]);
        float c0 = __int_as_float(e0.y), c1 = __int_as_float(e1.y);
        float c2 = __int_as_float(e2.y), c3 = __int_as_float(e3.y);
        a0.x += c0*v0.x; a0.y += c0*v0.y; a0.z += c0*v0.z; a0.w += c0*v0.w;
        a1.x += c1*v1.x; a1.y += c1*v1.y; a1.z += c1*v1.z; a1.w += c1*v1.w;
        a0.x += c2*v2.x; a0.y += c2*v2.y; a0.z += c2*v2.z; a0.w += c2*v2.w;
        a1.x += c3*v3.x; a1.y += c3*v3.y; a1.z += c3*v3.z; a1.w += c3*v3.w;
    }
    if (i < end) {
        int2 e0 = edges[i],   e1 = edges[i+1];
        int2 e2 = edges[i+2], e3 = edges[i+3];
        float4 v0 = *reinterpret_cast<const float4*>(&t[(size_t)e0.x * DIM + col]);
        float4 v1 = *reinterpret_cast<const float4*>(&t[(size_t)e1.x * DIM + col]);
        float4 v2 = *reinterpret_cast<const float4*>(&t[(size_t)e2.x * DIM + col]);
        float4 v3 = *reinterpret_cast<const float4*>(&t[(size_t)e3.x * DIM + col]);
        float c0 = __int_as_float(e0.y);
        float c1 = (i + 1 < end) ? __int_as_float(e1.y) : 0.0f;
        float c2 = (i + 2 < end) ? __int_as_float(e2.y) : 0.0f;
        float c3 = (i + 3 < end) ? __int_as_float(e3.y) : 0.0f;
        a0.x += c0*v0.x; a0.y += c0*v0.y; a0.z += c0*v0.z; a0.w += c0*v0.w;
        a1.x += c1*v1.x; a1.y += c1*v1.y; a1.z += c1*v1.z; a1.w += c1*v1.w;
        a0.x += c2*v2.x; a0.y += c2*v2.y; a0.z += c2*v2.z; a0.w += c2*v2.w;
        a1.x += c3*v3.x; a1.y += c3*v3.y; a1.z += c3*v3.z; a1.w += c3*v3.w;
    }

    float4 sv = *reinterpret_cast<const float4*>(&t[(size_t)node * DIM + col]);
    float4 o = make_float4((a0.x + a1.x + dn * sv.x) * dn,
                           (a0.y + a1.y + dn * sv.y) * dn,
                           (a0.z + a1.z + dn * sv.z) * dn,
                           (a0.w + a1.w + dn * sv.w) * dn);
    if (ACT) {
        o.x = o.x * p_scale.x + p_shift.x;
        o.y = o.y * p_scale.y + p_shift.y;
        o.z = o.z * p_scale.z + p_shift.z;
        o.w = o.w * p_scale.w + p_shift.w;
        o.x = (o.x > 0.f) ? o.x : expm1f(o.x);
        o.y = (o.y > 0.f) ? o.y : expm1f(o.y);
        o.z = (o.z > 0.f) ? o.z : expm1f(o.z);
        o.w = (o.w > 0.f) ? o.w : expm1f(o.w);
    }
    *reinterpret_cast<float4*>(&outp[(size_t)node * DIM + col]) = o;
}

// ---------------- fused layer 2: aggregate H2 (dim32) -> gemm 32->64 ----------
__global__ void __launch_bounds__(256) k_agg_gemm2(
        const float* __restrict__ A,        // H2, dim 32
        const int* __restrict__ rowptr,
        const int2* __restrict__ edges,
        const float* __restrict__ dis,
        const float* __restrict__ W,        // W2 [32,64]
        const float* __restrict__ b,
        const float* __restrict__ bg, const float* __restrict__ bbe,
        const float* __restrict__ bm, const float* __restrict__ bv,
        float* __restrict__ outT) {
    constexpr int DIN = 32, DOUT = 64, R = 4;
    constexpr int OX  = DOUT / 4;        // 16
    constexpr int NPB = (256 / OX) * R;  // 64
    constexpr int XP  = 36;              // row stride (floats), 16B-aligned
    __shared__ __align__(16) float Ws[DIN * DOUT];    // 8 KB
    __shared__ __align__(16) float xs[NPB * XP];      // 9 KB
    __shared__ float sh_scale[DOUT];
    __shared__ float sh_shift[DOUT];

    const int tid = threadIdx.x;
    for (int i = tid; i < DIN * DOUT; i += 256) Ws[i] = W[i];
    if (tid < DOUT) {
        float s = bg[tid] * rsqrtf(bv[tid] + EPS);
        sh_scale[tid] = s;
        sh_shift[tid] = s * (b[tid] - bm[tid]) + bbe[tid];
    }

    // ---- gather phase: 8 warps x G=4 subwarps = 32 nodes per pass, 2 passes --
    const int base = blockIdx.x * NPB;
    const int warp = tid >> 5;
    const int lane = tid & 31;
    const int sub  = lane >> 3;          // 0..3
    const int sl   = lane & 7;           // 0..7
    const int col  = sl * 4;

#pragma unroll
    for (int pass = 0; pass < 2; ++pass) {
        int r = pass * 32 + warp * 4 + sub;
        int node = base + r;
        float4 o = make_float4(0.f, 0.f, 0.f, 0.f);
        if (node < NN) {
            const int beg = rowptr[node], end = rowptr[node + 1];
            const float dn = dis[node];
            float4 a0 = make_float4(0.f, 0.f, 0.f, 0.f);
            float4 a1 = make_float4(0.f, 0.f, 0.f, 0.f);
            int i = beg;
            for (; i + 4 <= end; i += 4) {
                int2 e0 = edges[i],   e1 = edges[i+1];
                int2 e2 = edges[i+2], e3 = edges[i+3];
                float4 v0 = *reinterpret_cast<const float4*>(&A[(size_t)e0.x * DIN + col]);
                float4 v1 = *reinterpret_cast<const float4*>(&A[(size_t)e1.x * DIN + col]);
                float4 v2 = *reinterpret_cast<const float4*>(&A[(size_t)e2.x * DIN + col]);
                float4 v3 = *reinterpret_cast<const float4*>(&A[(size_t)e3.x * DIN + col]);
                float c0 = __int_as_float(e0.y), c1 = __int_as_float(e1.y);
                float c2 = __int_as_float(e2.y), c3 = __int_as_float(e3.y);
                a0.x += c0*v0.x; a0.y += c0*v0.y; a0.z += c0*v0.z; a0.w += c0*v0.w;
                a1.x += c1*v1.x; a1.y += c1*v1.y; a1.z += c1*v1.z; a1.w += c1*v1.w;
                a0.x += c2*v2.x; a0.y += c2*v2.y; a0.z += c2*v2.z; a0.w += c2*v2.w;
                a1.x += c3*v3.x; a1.y += c3*v3.y; a1.z += c3*v3.z; a1.w += c3*v3.w;
            }
            if (i < end) {
                int2 e0 = edges[i],   e1 = edges[i+1];
                int2 e2 = edges[i+2], e3 = edges[i+3];
                float4 v0 = *reinterpret_cast<const float4*>(&A[(size_t)e0.x * DIN + col]);
                float4 v1 = *reinterpret_cast<const float4*>(&A[(size_t)e1.x * DIN + col]);
                float4 v2 = *reinterpret_cast<const float4*>(&A[(size_t)e2.x * DIN + col]);
                float4 v3 = *reinterpret_cast<const float4*>(&A[(size_t)e3.x * DIN + col]);
                float c0 = __int_as_float(e0.y);
                float c1 = (i + 1 < end) ? __int_as_float(e1.y) : 0.0f;
                float c2 = (i + 2 < end) ? __int_as_float(e2.y) : 0.0f;
                float c3 = (i + 3 < end) ? __int_as_float(e3.y) : 0.0f;
                a0.x += c0*v0.x; a0.y += c0*v0.y; a0.z += c0*v0.z; a0.w += c0*v0.w;
                a1.x += c1*v1.x; a1.y += c1*v1.y; a1.z += c1*v1.z; a1.w += c1*v1.w;
                a0.x += c2*v2.x; a0.y += c2*v2.y; a0.z += c2*v2.z; a0.w += c2*v2.w;
                a1.x += c3*v3.x; a1.y += c3*v3.y; a1.z += c3*v3.z; a1.w += c3*v3.w;
            }
            float4 sv = *reinterpret_cast<const float4*>(&A[(size_t)node * DIN + col]);
            o = make_float4((a0.x + a1.x + dn * sv.x) * dn,
                            (a0.y + a1.y + dn * sv.y) * dn,
                            (a0.z + a1.z + dn * sv.z) * dn,
                            (a0.w + a1.w + dn * sv.w) * dn);
        }
        *reinterpret_cast<float4*>(&xs[r * XP + col]) = o;
    }
    __syncthreads();

    // ---- gemm phase: R=4 rows per thread ------------------------------------
    const int ox = tid % OX;
    const int r0 = (tid / OX) * R;

    float4 acc[R];
#pragma unroll
    for (int j = 0; j < R; ++j) acc[j] = make_float4(0.f, 0.f, 0.f, 0.f);

#pragma unroll 4
    for (int k = 0; k < DIN; ++k) {
        float4 w = *reinterpret_cast<const float4*>(&Ws[k * DOUT + ox * 4]);
#pragma unroll
        for (int j = 0; j < R; ++j) {
            float xv = xs[(r0 + j) * XP + k];
            acc[j].x += xv * w.x; acc[j].y += xv * w.y;
            acc[j].z += xv * w.z; acc[j].w += xv * w.w;
        }
    }

    const float4 s4 = *reinterpret_cast<const float4*>(&sh_scale[ox * 4]);
    const float4 h4 = *reinterpret_cast<const float4*>(&sh_shift[ox * 4]);
#pragma unroll
    for (int j = 0; j < R; ++j) {
        int node = base + r0 + j;
        if (node >= NN) continue;
        float4 o = acc[j];
        o.x = o.x * s4.x + h4.x; o.y = o.y * s4.y + h4.y;
        o.z = o.z * s4.z + h4.z; o.w = o.w * s4.w + h4.w;
        o.x = (o.x > 0.f) ? o.x : expm1f(o.x);
        o.y = (o.y > 0.f) ? o.y : expm1f(o.y);
        o.z = (o.z > 0.f) ? o.z : expm1f(o.z);
        o.w = (o.w > 0.f) ? o.w : expm1f(o.w);
        *reinterpret_cast<float4*>(&outT[(size_t)node * DOUT + ox * 4]) = o;
    }
}

// ---------------- fused layer 3+4a: aggregate H3 (dim64) -> gemm3 -> W4 dot ---
__global__ void __launch_bounds__(256) k_agg_gemm3_dot(
        const float* __restrict__ T,        // H3, dim 64
        const int* __restrict__ rowptr,
        const int2* __restrict__ edges,
        const float* __restrict__ dis,
        const float* __restrict__ W,        // W3 [64,128]
        const float* __restrict__ b,
        const float* __restrict__ bg, const float* __restrict__ bbe,
        const float* __restrict__ bm, const float* __restrict__ bv,
        const float* __restrict__ W4,
        float* __restrict__ t4) {
    constexpr int DIN = 64, DOUT = 128, R = 4;
    constexpr int OX  = DOUT / 4;        // 32
    constexpr int NPB = (256 / OX) * R;  // 32
    constexpr int XP  = 68;              // row stride (floats), 16B-aligned
    __shared__ __align__(16) float Ws[DIN * DOUT];    // 32 KB
    __shared__ __align__(16) float xs[NPB * XP];      // 8.7 KB
    __shared__ float sh_scale[DOUT];
    __shared__ float sh_shift[DOUT];
    __shared__ __align__(16) float w4s[DOUT];

    const int tid = threadIdx.x;
    for (int i = tid; i < DIN * DOUT; i += 256) Ws[i] = W[i];
    if (tid < DOUT) {
        float s = bg[tid] * rsqrtf(bv[tid] + EPS);
        sh_scale[tid] = s;
        sh_shift[tid] = s * (b[tid] - bm[tid]) + bbe[tid];
        w4s[tid] = W4[tid];
    }

    // ---- gather phase: 8 warps x G=2 subwarps = 16 nodes per pass, 2 passes --
    const int base = blockIdx.x * NPB;
    const int warp = tid >> 5;
    const int lane = tid & 31;
    const int sub  = lane >> 4;          // 0..1
    const int sl   = lane & 15;          // 0..15
    const int col  = sl * 4;

#pragma unroll
    for (int pass = 0; pass < 2; ++pass) {
        int r = pass * 16 + warp * 2 + sub;
        int node = base + r;
        float4 o = make_float4(0.f, 0.f, 0.f, 0.f);
        if (node < NN) {
            const int beg = rowptr[node], end = rowptr[node + 1];
            const float dn = dis[node];
            float4 a0 = make_float4(0.f, 0.f, 0.f, 0.f);
            float4 a1 = make_float4(0.f, 0.f, 0.f, 0.f);
            int i = beg;
            for (; i + 4 <= end; i += 4) {
                int2 e0 = edges[i],   e1 = edges[i+1];
                int2 e2 = edges[i+2], e3 = edges[i+3];
                float4 v0 = *reinterpret_cast<const float4*>(&T[(size_t)e0.x * DIN + col]);
                float4 v1 = *reinterpret_cast<const float4*>(&T[(size_t)e1.x * DIN + col]);
                float4 v2 = *reinterpret_cast<const float4*>(&T[(size_t)e2.x * DIN + col]);
                float4 v3 = *reinterpret_cast<const float4*>(&T[(size_t)e3.x * DIN + col]);
                float c0 = __int_as_float(e0.y), c1 = __int_as_float(e1.y);
                float c2 = __int_as_float(e2.y), c3 = __int_as_float(e3.y);
                a0.x += c0*v0.x; a0.y += c0*v0.y; a0.z += c0*v0.z; a0.w += c0*v0.w;
                a1.x += c1*v1.x; a1.y += c1*v1.y; a1.z += c1*v1.z; a1.w += c1*v1.w;
                a0.x += c2*v2.x; a0.y += c2*v2.y; a0.z += c2*v2.z; a0.w += c2*v2.w;
                a1.x += c3*v3.x; a1.y += c3*v3.y; a1.z += c3*v3.z; a1.w += c3*v3.w;
            }
            if (i < end) {
                int2 e0 = edges[i],   e1 = edges[i+1];
                int2 e2 = edges[i+2], e3 = edges[i+3];
                float4 v0 = *reinterpret_cast<const float4*>(&T[(size_t)e0.x * DIN + col]);
                float4 v1 = *reinterpret_cast<const float4*>(&T[(size_t)e1.x * DIN + col]);
                float4 v2 = *reinterpret_cast<const float4*>(&T[(size_t)e2.x * DIN + col]);
                float4 v3 = *reinterpret_cast<const float4*>(&T[(size_t)e3.x * DIN + col]);
                float c0 = __int_as_float(e0.y);
                float c1 = (i + 1 < end) ? __int_as_float(e1.y) : 0.0f;
                float c2 = (i + 2 < end) ? __int_as_float(e2.y) : 0.0f;
                float c3 = (i + 3 < end) ? __int_as_float(e3.y) : 0.0f;
                a0.x += c0*v0.x; a0.y += c0*v0.y; a0.z += c0*v0.z; a0.w += c0*v0.w;
                a1.x += c1*v1.x; a1.y += c1*v1.y; a1.z += c1*v1.z; a1.w += c1*v1.w;
                a0.x += c2*v2.x; a0.y += c2*v2.y; a0.z += c2*v2.z; a0.w += c2*v2.w;
                a1.x += c3*v3.x; a1.y += c3*v3.y; a1.z += c3*v3.z; a1.w += c3*v3.w;
            }
            float4 sv = *reinterpret_cast<const float4*>(&T[(size_t)node * DIN + col]);
            o = make_float4((a0.x + a1.x + dn * sv.x) * dn,
                            (a0.y + a1.y + dn * sv.y) * dn,
                            (a0.z + a1.z + dn * sv.z) * dn,
                            (a0.w + a1.w + dn * sv.w) * dn);
        }
        *reinterpret_cast<float4*>(&xs[r * XP + col]) = o;
    }
    __syncthreads();

    // ---- gemm + bn3 + elu + W4 dot phase ------------------------------------
    const int ox = tid % OX;             // == lane
    const int r0 = (tid / OX) * R;

    float4 acc[R];
#pragma unroll
    for (int j = 0; j < R; ++j) acc[j] = make_float4(0.f, 0.f, 0.f, 0.f);

#pragma unroll 4
    for (int k = 0; k < DIN; ++k) {
        float4 w = *reinterpret_cast<const float4*>(&Ws[k * DOUT + ox * 4]);
#pragma unroll
        for (int j = 0; j < R; ++j) {
            float xv = xs[(r0 + j) * XP + k];
            acc[j].x += xv * w.x; acc[j].y += xv * w.y;
            acc[j].z += xv * w.z; acc[j].w += xv * w.w;
        }
    }

    const float4 s4 = *reinterpret_cast<const float4*>(&sh_scale[ox * 4]);
    const float4 h4 = *reinterpret_cast<const float4*>(&sh_shift[ox * 4]);
    const float4 w4 = *reinterpret_cast<const float4*>(&w4s[ox * 4]);
#pragma unroll
    for (int j = 0; j < R; ++j) {
        float4 o = acc[j];
        o.x = o.x * s4.x + h4.x; o.y = o.y * s4.y + h4.y;
        o.z = o.z * s4.z + h4.z; o.w = o.w * s4.w + h4.w;
        o.x = (o.x > 0.f) ? o.x : expm1f(o.x);
        o.y = (o.y > 0.f) ? o.y : expm1f(o.y);
        o.z = (o.z > 0.f) ? o.z : expm1f(o.z);
        o.w = (o.w > 0.f) ? o.w : expm1f(o.w);
        float p = o.x * w4.x + o.y * w4.y + o.z * w4.z + o.w * w4.w;
#pragma unroll
        for (int sh = 16; sh > 0; sh >>= 1)
            p += __shfl_xor_sync(0xffffffffu, p, sh);
        int node = base + r0 + j;
        if (ox == 0 && node < NN) t4[node] = p;
    }
}

__global__ void __launch_bounds__(256) k_gather1_final(const float* __restrict__ t4,
                                const int* __restrict__ rowptr,
                                const int2* __restrict__ edges,
                                const float* __restrict__ dis,
                                const float* __restrict__ b4,
                                float* __restrict__ out) {
    const int warp = (blockIdx.x * blockDim.x + threadIdx.x) >> 5;
    const int lane = threadIdx.x & 31;
    if (warp >= NN) return;
    const int node = warp;
    const int beg = rowptr[node], end = rowptr[node + 1];
    float acc = 0.0f;
    for (int i = beg + lane; i < end; i += 32) {
        int2 e = edges[i];
        acc += __int_as_float(e.y) * t4[e.x];
    }
#pragma unroll
    for (int o = 16; o > 0; o >>= 1) acc += __shfl_xor_sync(0xffffffffu, acc, o);
    if (lane == 0) {
        float dn = dis[node];
        float x = (acc + dn * t4[node]) * dn + b4[0];
        x = (x > 0.0f) ? x : expm1f(x);
        out[node] = 1.0f / (1.0f + expf(-x));
    }
}

// ---------------- launch -----------------------------------------------------
extern "C" void kernel_launch(void* const* d_in, const int* in_sizes, int n_in,
                              void* d_out, int out_size) {
    const float* x   = (const float*)d_in[0];
    const int*   src = (const int*)  d_in[1];
    const int*   dst = (const int*)  d_in[2];
    const float* W1 = (const float*)d_in[3];  const float* b1 = (const float*)d_in[4];
    const float* W2 = (const float*)d_in[5];  const float* b2 = (const float*)d_in[6];
    const float* W3 = (const float*)d_in[7];  const float* b3 = (const float*)d_in[8];
    const float* W4 = (const float*)d_in[9];  const float* b4 = (const float*)d_in[10];
    const float* g1 = (const float*)d_in[11]; const float* be1 = (const float*)d_in[12];
    const float* m1 = (const float*)d_in[13]; const float* v1  = (const float*)d_in[14];
    const float* g2 = (const float*)d_in[15]; const float* be2 = (const float*)d_in[16];
    const float* m2 = (const float*)d_in[17]; const float* v2  = (const float*)d_in[18];
    const float* g3 = (const float*)d_in[19]; const float* be3 = (const float*)d_in[20];
    const float* m3 = (const float*)d_in[21]; const float* v3  = (const float*)d_in[22];
    float* out = (float*)d_out;

    void *pcnt, *ppart, *prp, *pcur, *pdis, *pedge, *pT, *pA, *pt4;
    cudaGetSymbolAddress(&pcnt, g_cnt);
    cudaGetSymbolAddress(&ppart, g_part);
    cudaGetSymbolAddress(&prp,  g_rowptr);
    cudaGetSymbolAddress(&pcur, g_cursor);
    cudaGetSymbolAddress(&pdis, g_dis);
    cudaGetSymbolAddress(&pedge, g_edge);
    cudaGetSymbolAddress(&pT, g_T);
    cudaGetSymbolAddress(&pA, g_A);
    cudaGetSymbolAddress(&pt4, g_t4);
    int* cnt = (int*)pcnt; int* part = (int*)ppart;
    int* rowptr = (int*)prp; int* cursor = (int*)pcur;
    float* dis = (float*)pdis;
    int2* edges = (int2*)pedge;
    float* T = (float*)pT; float* A = (float*)pA;
    float* t4 = (float*)pt4;

    const int TB = 256;
    const int gE = (NE + TB - 1) / TB;
    const int gW = (NN + 7) / 8;                 // warp-per-node kernels
    const int gW4 = (NN + 4 * 8 - 1) / (4 * 8);  // G=4 sub-warp gather (dim 32)
    const int NBLK = (NN + 1023) / 1024;         // 98 scan blocks

    const int SM1 = (128*32 + 128*65) * 4;   // 49664 bytes dynamic smem for gemm1
    cudaFuncSetAttribute((const void*)k_gemm1_count,
                         cudaFuncAttributeMaxDynamicSharedMemorySize, SM1);

    // (1) gemm1 (x@W1 -> T, R=4 K-chunked) fused with degree count
    k_gemm1_count<<<(NN + 127) / 128, TB, SM1>>>(x, W1, T, dst, cnt);
    // (2,3) multi-block scan
    k_scan_part<<<NBLK, 1024>>>(cnt, part);
    k_scan_apply<<<NBLK, 1024>>>(cnt, part, rowptr, cursor, dis);
    // (4) permute  [profiled control]
    k_permute<<<gE, TB>>>(src, dst, dis, cursor, edges);

    // layer 1 gather dim32 (G=4) + bias+bn1+elu -> H2 (A)
    k_gatherG<32, 4, true><<<gW4, TB>>>(T, rowptr, edges, dis, b1, g1, be1, m1, v1, A);

    // layer 2 fused: aggregate H2 (dim32) into smem, gemm 32->64 + bn2+elu -> T
    k_agg_gemm2<<<(NN + 63) / 64, TB>>>(A, rowptr, edges, dis,
                                        W2, b2, g2, be2, m2, v2, T);

    // layer 3+4a fused: aggregate H3 (dim64) into smem, gemm3 + bn3+elu + W4 dot -> t4
    k_agg_gemm3_dot<<<(NN + 31) / 32, TB>>>(T, rowptr, edges, dis,
                                            W3, b3, g3, be3, m3, v3, W4, t4);

    // layer 4 final gather + elu + sigmoid
    k_gather1_final<<<gW, TB>>>(t4, rowptr, edges, dis, b4, out);
}